// round 1
// baseline (speedup 1.0000x reference)
#include <cuda_runtime.h>

// MetapathGATConv fused kernel (fp32, packed f32x2 FMA).
// One CTA handles NB=8 nodes. All intermediates live in SMEM.
//
// Per node (R=8 relation rows, D=256, H=4 heads x C=64):
//   h0 = relu(x)                                 [8,256]
//   xl0 = h0 @ Wl0 + bl0 ; xr0 = h0 @ Wr0 + br0  [8,256] each
//   logits0[i,j,h] = sum_c att0[h,c]*leaky(xr0[i,hc]+xl0[j,hc]); softmax over j
//   h1 = relu(sum_j alpha0[i,j,h]*xl0[j,:] + bias0)
//   xl1 = h1 @ Wl1 + bl1 ; xr1 = h1[7] @ Wr1 + br1
//   logits1[r,h] = sum_c att1[h,c]*leaky(xr1[hc]+xl1[r,hc]); softmax over r = beta
//   out = relu(sum_r beta[r,h]*xl1[r,:] + bias1)
// Outputs: node_embs [N,256] then betas [N,8,4] concatenated in d_out.

#define RREL   8
#define EMBED  256
#define NB     8            // nodes per CTA
#define ROWS   (NB * RREL)  // 64
#define PITCH  260          // SMEM row pitch (floats): 4-bank skew per row, float4 aligned
#define NTHREADS 512

typedef unsigned long long ull;

__device__ __forceinline__ ull packf2(float lo, float hi) {
    ull r;
    asm("mov.b64 %0, {%1, %2};" : "=l"(r) : "f"(lo), "f"(hi));
    return r;
}
__device__ __forceinline__ void unpackf2(ull v, float& lo, float& hi) {
    asm("mov.b64 {%0, %1}, %2;" : "=f"(lo), "=f"(hi) : "l"(v));
}
__device__ __forceinline__ void fma2(ull& d, ull a, ull b) {
    asm("fma.rn.f32x2 %0, %1, %2, %0;" : "+l"(d) : "l"(a), "l"(b));
}

__device__ __forceinline__ float leaky(float v) {
    return v > 0.f ? v : 0.2f * v;
}

// C[row, col] = sum_k A[row,k] * W[k*256+col] + bias[col]
// Each thread owns one output column `col` for NR rows (rbase + r*RSTEP).
// A, C are SMEM with PITCH; W, bias are global (L2-resident).
template <int NR, int RSTEP>
__device__ __forceinline__ void gemm_cols(
    const float* __restrict__ W, const float* __restrict__ bias,
    const float* __restrict__ A, float* __restrict__ C,
    int col, int rbase)
{
    ull acc[NR];
    float bv = bias[col];
#pragma unroll
    for (int r = 0; r < NR; r++) acc[r] = packf2(bv, 0.f);

    float4 w;
    w.x = W[0 * EMBED + col]; w.y = W[1 * EMBED + col];
    w.z = W[2 * EMBED + col]; w.w = W[3 * EMBED + col];

#pragma unroll 2
    for (int k = 0; k < EMBED; k += 4) {
        float4 wn = make_float4(0.f, 0.f, 0.f, 0.f);
        if (k + 4 < EMBED) {
            wn.x = W[(k + 4) * EMBED + col]; wn.y = W[(k + 5) * EMBED + col];
            wn.z = W[(k + 6) * EMBED + col]; wn.w = W[(k + 7) * EMBED + col];
        }
        ull b01 = packf2(w.x, w.y);
        ull b23 = packf2(w.z, w.w);
#pragma unroll
        for (int r = 0; r < NR; r++) {
            const ulonglong2* ap = reinterpret_cast<const ulonglong2*>(
                A + (rbase + r * RSTEP) * PITCH + k);
            ulonglong2 av = *ap;   // (A[row,k], A[row,k+1]) | (A[row,k+2], A[row,k+3])
            fma2(acc[r], av.x, b01);
            fma2(acc[r], av.y, b23);
        }
        w = wn;
    }
#pragma unroll
    for (int r = 0; r < NR; r++) {
        float lo, hi;
        unpackf2(acc[r], lo, hi);
        C[(rbase + r * RSTEP) * PITCH + col] = lo + hi;
    }
}

extern "C" __global__ void __launch_bounds__(NTHREADS, 1)
metapath_gat_kernel(
    const float* __restrict__ x,
    const float* __restrict__ Wl0, const float* __restrict__ bl0,
    const float* __restrict__ Wr0, const float* __restrict__ br0,
    const float* __restrict__ att0, const float* __restrict__ bias0,
    const float* __restrict__ Wl1, const float* __restrict__ bl1,
    const float* __restrict__ Wr1, const float* __restrict__ br1,
    const float* __restrict__ att1, const float* __restrict__ bias1,
    float* __restrict__ outEmb, float* __restrict__ outBeta)
{
    extern __shared__ float smem[];
    float* bufH   = smem;                      // [64][260]  h0 then h1
    float* bufXL  = bufH + ROWS * PITCH;       // [64][260]  xl0 then xl1
    float* bufXR  = bufXL + ROWS * PITCH;      // [64][260]  xr0 then xr1(self rows)
    float* alphaS = bufXR + ROWS * PITCH;      // [8][8][8][4] = 2048
    float* betaS  = alphaS + 2048;             // [8][8][4]   = 256
    float* attS   = betaS + 256;               // att0 | att1 = 512

    const int tid = threadIdx.x;
    const int g = blockIdx.x;
    const float* xg = x + (size_t)g * (NB * RREL * EMBED);

    if (tid < 512) attS[tid] = (tid < 256) ? att0[tid] : att1[tid - 256];

    // ---- Phase 1: load x -> relu -> bufH ----
#pragma unroll
    for (int i = 0; i < 8; i++) {
        int idx = tid + i * NTHREADS;          // 0..4095 float4s
        float4 v = reinterpret_cast<const float4*>(xg)[idx];
        int f = idx * 4;
        int r = f >> 8;
        int d = f & 255;
        v.x = fmaxf(v.x, 0.f); v.y = fmaxf(v.y, 0.f);
        v.z = fmaxf(v.z, 0.f); v.w = fmaxf(v.w, 0.f);
        *reinterpret_cast<float4*>(&bufH[r * PITCH + d]) = v;
    }
    __syncthreads();

    const int col  = tid & 255;
    const int half = tid >> 8;   // 0/1 : row-halves for GEMMs, node-halves elsewhere

    // ---- Phase 2: layer-0 GEMMs (xl0, xr0) ----
    gemm_cols<32, 1>(Wl0, bl0, bufH, bufXL, col, half * 32);
    gemm_cols<32, 1>(Wr0, br0, bufH, bufXR, col, half * 32);
    __syncthreads();

    // ---- Phase 3: logits0 + softmax over j -> alphaS ----
    {
        int w = tid >> 5, lane = tid & 31;
        int node = w & 7, ihalf = w >> 3;      // warp -> (node, i-half)
        int j = lane >> 2, h = lane & 3;       // lane -> (src j, head h)
        const float* att = attS + h * 64;
        const float* xlrow = bufXL + (node * 8 + j) * PITCH + h * 64;
#pragma unroll
        for (int ii = 0; ii < 4; ii++) {
            int i = ihalf * 4 + ii;
            const float* xrrow = bufXR + (node * 8 + i) * PITCH + h * 64;
            float s = 0.f;
#pragma unroll 8
            for (int c = 0; c < 64; c++)
                s += att[c] * leaky(xrrow[c] + xlrow[c]);
            float m = s;
            m = fmaxf(m, __shfl_xor_sync(0xffffffffu, m, 4));
            m = fmaxf(m, __shfl_xor_sync(0xffffffffu, m, 8));
            m = fmaxf(m, __shfl_xor_sync(0xffffffffu, m, 16));
            float e = __expf(s - m);
            float sum = e;
            sum += __shfl_xor_sync(0xffffffffu, sum, 4);
            sum += __shfl_xor_sync(0xffffffffu, sum, 8);
            sum += __shfl_xor_sync(0xffffffffu, sum, 16);
            alphaS[((node * 8 + i) * 8 + j) * 4 + h] = e / sum;
        }
    }
    __syncthreads();

    // ---- Phase 4: aggregate h1 = relu(alpha @ xl0 + bias0) -> bufH ----
    {
        int h = col >> 6;
        float b0 = bias0[col];
#pragma unroll
        for (int nn = 0; nn < 4; nn++) {
            int nd = half * 4 + nn;
            float xlv[8];
#pragma unroll
            for (int j = 0; j < 8; j++) xlv[j] = bufXL[(nd * 8 + j) * PITCH + col];
#pragma unroll
            for (int i = 0; i < 8; i++) {
                float s = b0;
#pragma unroll
                for (int j = 0; j < 8; j++)
                    s += alphaS[((nd * 8 + i) * 8 + j) * 4 + h] * xlv[j];
                bufH[(nd * 8 + i) * PITCH + col] = fmaxf(s, 0.f);
            }
        }
    }
    __syncthreads();

    // ---- Phase 5: layer-1 GEMMs: xl1 -> bufXL; xr1(self rows nd*8+7) -> bufXR ----
    gemm_cols<32, 1>(Wl1, bl1, bufH, bufXL, col, half * 32);
    gemm_cols<4, 8>(Wr1, br1, bufH, bufXR, col, half * 4 * 8 + 7);
    __syncthreads();

    // ---- Phase 6: logits1 + softmax over r -> beta (smem + global) ----
    if (tid < 256) {
        int node = tid >> 5, lane = tid & 31;
        int r = lane >> 2, h = lane & 3;
        const float* att = attS + 256 + h * 64;
        const float* xr = bufXR + (node * 8 + 7) * PITCH + h * 64;
        const float* xl = bufXL + (node * 8 + r) * PITCH + h * 64;
        float s = 0.f;
#pragma unroll 8
        for (int c = 0; c < 64; c++)
            s += att[c] * leaky(xr[c] + xl[c]);
        float m = s;
        m = fmaxf(m, __shfl_xor_sync(0xffffffffu, m, 4));
        m = fmaxf(m, __shfl_xor_sync(0xffffffffu, m, 8));
        m = fmaxf(m, __shfl_xor_sync(0xffffffffu, m, 16));
        float e = __expf(s - m);
        float sum = e;
        sum += __shfl_xor_sync(0xffffffffu, sum, 4);
        sum += __shfl_xor_sync(0xffffffffu, sum, 8);
        sum += __shfl_xor_sync(0xffffffffu, sum, 16);
        float beta = e / sum;
        betaS[(node * 8 + r) * 4 + h] = beta;
        outBeta[(size_t)(g * 8 + node) * 32 + r * 4 + h] = beta;
    }
    __syncthreads();

    // ---- Phase 7: out = relu(beta @ xl1 + bias1) -> global ----
    {
        int h = col >> 6;
        float b1 = bias1[col];
#pragma unroll
        for (int nn = 0; nn < 4; nn++) {
            int nd = half * 4 + nn;
            float s = b1;
#pragma unroll
            for (int r = 0; r < 8; r++)
                s += betaS[(nd * 8 + r) * 4 + h] * bufXL[(nd * 8 + r) * PITCH + col];
            outEmb[(size_t)(g * 8 + nd) * 256 + col] = fmaxf(s, 0.f);
        }
    }
}

extern "C" void kernel_launch(void* const* d_in, const int* in_sizes, int n_in,
                              void* d_out, int out_size)
{
    const float* x     = (const float*)d_in[0];
    const float* Wl0   = (const float*)d_in[1];
    const float* bl0   = (const float*)d_in[2];
    const float* Wr0   = (const float*)d_in[3];
    const float* br0   = (const float*)d_in[4];
    const float* att0  = (const float*)d_in[5];
    const float* bias0 = (const float*)d_in[6];
    const float* Wl1   = (const float*)d_in[7];
    const float* bl1   = (const float*)d_in[8];
    const float* Wr1   = (const float*)d_in[9];
    const float* br1   = (const float*)d_in[10];
    const float* att1  = (const float*)d_in[11];
    const float* bias1 = (const float*)d_in[12];

    int nodes = in_sizes[0] / (RREL * EMBED);   // 16384
    float* outEmb  = (float*)d_out;
    float* outBeta = outEmb + (size_t)nodes * EMBED;

    size_t smem_bytes = (size_t)(3 * ROWS * PITCH + 2048 + 256 + 512) * sizeof(float);
    cudaFuncSetAttribute(metapath_gat_kernel,
                         cudaFuncAttributeMaxDynamicSharedMemorySize,
                         (int)smem_bytes);

    dim3 grid(nodes / NB);
    metapath_gat_kernel<<<grid, NTHREADS, smem_bytes>>>(
        x, Wl0, bl0, Wr0, br0, att0, bias0,
        Wl1, bl1, Wr1, br1, att1, bias1,
        outEmb, outBeta);
}